// round 15
// baseline (speedup 1.0000x reference)
#include <cuda_runtime.h>
#include <cuda_fp16.h>
#include <math.h>
#include <stdint.h>

#define BATCH   2
#define SEQ     2048
#define DMODEL  1024
#define NHEADS  16
#define HDIM    64
#define M_ROWS  (BATCH*SEQ)
#define ROPE_SCALE 0.006135923151542565f      // 2*pi/1024
#define LOG2_1E4_OVER16 0.830482023721841f    // log2(10000)/16
#define QSCALE 0.1803368801111204f            // 0.125 * log2(e)

// Scratch (device globals: allocation-free)
__device__ __half g_q[BATCH*NHEADS*SEQ*HDIM];   // [B,H,N,D] fp16, *0.125*log2e, roped
__device__ __half g_k[BATCH*NHEADS*SEQ*HDIM];   // [B,H,N,D] fp16, roped
__device__ __half g_v[BATCH*NHEADS*HDIM*SEQ];   // [B,H,D,N] fp16 TRANSPOSED
__device__ __half g_o[BATCH*SEQ*DMODEL];        // [B,N,d] fp16
__device__ __half g_xh[M_ROWS*DMODEL];          // x as fp16
__device__ __half g_wh[4*DMODEL*DMODEL];        // Wq,Wk,Wv,Wo as fp16

// ---------------------------------------------------------------------------
// helpers
// ---------------------------------------------------------------------------
__device__ __forceinline__ float fast_exp2(float x) {
    float y;
    asm("ex2.approx.f32 %0, %1;" : "=f"(y) : "f"(x));
    return y;
}
__device__ __forceinline__ uint32_t smem_u32(const void* p) {
    uint32_t a;
    asm("{ .reg .u64 t; cvta.to.shared.u64 t, %1; cvt.u32.u64 %0, t; }"
        : "=r"(a) : "l"(p));
    return a;
}
__device__ __forceinline__ void cp_async16(uint32_t dst, const void* src) {
    asm volatile("cp.async.cg.shared.global [%0], [%1], 16;" :: "r"(dst), "l"(src));
}
#define CP_COMMIT()  asm volatile("cp.async.commit_group;" ::: "memory")
#define CP_WAIT_1()  asm volatile("cp.async.wait_group 1;" ::: "memory")
#define CP_WAIT_0()  asm volatile("cp.async.wait_group 0;" ::: "memory")

__device__ __forceinline__ uint32_t pack_h2(float a, float b) {
    __half2 h = __floats2half2_rn(a, b);
    return *(uint32_t*)&h;
}
__device__ __forceinline__ uint32_t h2exp2_u32(uint32_t x) {
    uint32_t y;
    asm("ex2.approx.f16x2 %0, %1;" : "=r"(y) : "r"(x));
    return y;
}

__device__ __forceinline__ void ldsm_x4(uint32_t* r, uint32_t addr) {
    asm volatile("ldmatrix.sync.aligned.m8n8.x4.shared.b16 {%0,%1,%2,%3}, [%4];"
        : "=r"(r[0]), "=r"(r[1]), "=r"(r[2]), "=r"(r[3]) : "r"(addr));
}

// m16n8k16 fp16 MMA, fp32 accumulate
__device__ __forceinline__ void mma_f16(float c[4], const uint32_t a[4],
                                        uint32_t b0, uint32_t b1)
{
    asm volatile(
        "mma.sync.aligned.m16n8k16.row.col.f32.f16.f16.f32 "
        "{%0,%1,%2,%3}, {%4,%5,%6,%7}, {%8,%9}, {%0,%1,%2,%3};\n"
        : "+f"(c[0]), "+f"(c[1]), "+f"(c[2]), "+f"(c[3])
        : "r"(a[0]), "r"(a[1]), "r"(a[2]), "r"(a[3]), "r"(b0), "r"(b1));
}

#define ONES_H2 0x3C003C00u   // (1.0h, 1.0h)

// ---------------------------------------------------------------------------
// merged fp16 pre-convert
// ---------------------------------------------------------------------------
struct CvtArgs { const float4* src[5]; };
#define NX4 (M_ROWS*DMODEL/4)
#define NW4 (DMODEL*DMODEL/4)

__global__ void cvt_all_kernel(CvtArgs a, uint2* __restrict__ dstX,
                               uint2* __restrict__ dstW)
{
    int i = blockIdx.x * blockDim.x + threadIdx.x;
    float4 v;
    uint2* d;
    if (i < NX4) {
        v = a.src[0][i];
        d = dstX + i;
    } else {
        int j = i - NX4;
        v = a.src[1 + (j >> 18)][j & (NW4 - 1)];
        d = dstW + j;
    }
    *d = make_uint2(pack_h2(v.x, v.y), pack_h2(v.z, v.w));
}

// ---------------------------------------------------------------------------
// fp16 mma GEMM (unchanged): cp.async + ldmatrix, 3-stage pipeline.
// ---------------------------------------------------------------------------
struct GemmArgs {
    const __half* A;
    const __half* W[3];
    const float*  bias[3];
    void*         C[3];
    const float*  pos[3];
    int layout_bhnd;
};

#define G_STG 32768
#define GEMM_SMEM (3*G_STG)

__global__ __launch_bounds__(256, 2)
void gemm_mma_kernel(GemmArgs args)
{
    extern __shared__ __align__(128) uint8_t smem[];
    const uint32_t sb = smem_u32(smem);

    const int tid  = threadIdx.x;
    const int warp = tid >> 5;
    const int lane = tid & 31;
    const int wm = (warp & 1) * 64;
    const int wn = (warp >> 1) * 32;
    const int proj = blockIdx.x >> 3;
    const int bn   = (blockIdx.x & 7) * 128;
    const int bm   = blockIdx.y * 128;

    const __half* A    = args.A;
    const __half* W    = args.W[proj];
    const float*  bias = args.bias[proj];
    const float*  pos  = args.pos[proj];

    const int cc = tid & 7;
    const int cr = tid >> 3;
    const __half* gA = A + (size_t)(bm + cr) * DMODEL + cc * 8;
    const __half* gB = W + (size_t)(bn + cr) * DMODEL + cc * 8;
    uint32_t cdst[4];
#pragma unroll
    for (int i = 0; i < 4; i++) {
        int R = cr + 32 * i;
        cdst[i] = R * 128 + ((cc ^ (R & 7)) << 4);
    }

#define GEMM_COPY(tile, stage) do { \
    uint32_t _sA = sb + (stage) * G_STG; \
    uint32_t _sB = _sA + 16384; \
    const __half* _ga = gA + (size_t)(tile) * 64; \
    const __half* _gb = gB + (size_t)(tile) * 64; \
    _Pragma("unroll") \
    for (int i = 0; i < 4; i++) { \
        cp_async16(_sA + cdst[i], _ga + (size_t)i * 32 * DMODEL); \
        cp_async16(_sB + cdst[i], _gb + (size_t)i * 32 * DMODEL); \
    } \
} while (0)

    float acc[4][4][4];
#pragma unroll
    for (int mt = 0; mt < 4; mt++)
#pragma unroll
        for (int nt = 0; nt < 4; nt++)
#pragma unroll
            for (int r = 0; r < 4; r++) acc[mt][nt][r] = 0.f;

    GEMM_COPY(0, 0); CP_COMMIT();
    GEMM_COPY(1, 1); CP_COMMIT();

    const int q = lane & 3;
    const int s = lane >> 2;

    const int rlow = lane & 7;
    const int hbit = (lane >> 3) & 1;
    const int qbit = (lane >> 4) & 1;
    uint32_t aSw[4], bSw[4];
#pragma unroll
    for (int kbi = 0; kbi < 4; kbi++) {
        aSw[kbi] = ((uint32_t)((2 * kbi + qbit) ^ rlow)) << 4;
        bSw[kbi] = ((uint32_t)((2 * kbi + hbit) ^ rlow)) << 4;
    }
    const uint32_t aRb = (uint32_t)(wm + hbit * 8 + rlow) * 128;
    const uint32_t bRb = (uint32_t)(wn + qbit * 8 + rlow) * 128 + 16384;

    int ms = 0, ps = 2;
#pragma unroll 1
    for (int k0 = 0; k0 < 16; k0++) {
        if (k0 < 15) CP_WAIT_1(); else CP_WAIT_0();
        __syncthreads();
        if (k0 + 2 < 16) { GEMM_COPY(k0 + 2, ps); CP_COMMIT(); }

        const uint32_t soff = sb + ms * G_STG;

#pragma unroll
        for (int kbi = 0; kbi < 4; kbi++) {
            uint32_t af[4][4];
#pragma unroll
            for (int mt = 0; mt < 4; mt++)
                ldsm_x4(af[mt], soff + aRb + mt * 2048 + aSw[kbi]);
            uint32_t bf[2][4];
#pragma unroll
            for (int ntp = 0; ntp < 2; ntp++)
                ldsm_x4(bf[ntp], soff + bRb + ntp * 2048 + bSw[kbi]);
#pragma unroll
            for (int nt = 0; nt < 4; nt++) {
                uint32_t b0 = bf[nt >> 1][(nt & 1) * 2];
                uint32_t b1 = bf[nt >> 1][(nt & 1) * 2 + 1];
#pragma unroll
                for (int mt = 0; mt < 4; mt++)
                    mma_f16(acc[mt][nt], af[mt], b0, b1);
            }
        }
        ms = (ms == 2) ? 0 : ms + 1;
        ps = (ps == 2) ? 0 : ps + 1;
    }

    // epilogue
    const float scl = (proj == 0 && args.layout_bhnd) ? QSCALE : 1.0f;
#pragma unroll
    for (int nt = 0; nt < 4; nt++) {
        int cg = bn + wn + nt * 8 + 2 * q;
        float bv0 = bias[cg], bv1 = bias[cg + 1];
        int dd = cg & 63;
        int hh = (cg >> 6) & (NHEADS - 1);
        int ip = (dd & 31) >> 1;
        int plane = (dd >> 5) & 1;
        float invf = fast_exp2(-LOG2_1E4_OVER16 * (float)ip) * ROPE_SCALE;
#pragma unroll
        for (int mt = 0; mt < 4; mt++) {
            int r0 = bm + wm + mt * 16 + s;
#pragma unroll
            for (int rr = 0; rr < 2; rr++) {
                int r = r0 + rr * 8;
                float v0 = acc[mt][nt][rr * 2 + 0] + bv0;
                float v1 = acc[mt][nt][rr * 2 + 1] + bv1;
                if (args.layout_bhnd) {
                    int b = r >> 11, n = r & 2047;
                    if (pos) {
                        float ang = pos[((size_t)(b * SEQ + n)) * 2 + plane] * invf;
                        float sn, cs;
                        __sincosf(ang, &sn, &cs);
                        float y0 = v0 * cs - v1 * sn;
                        float y1 = v0 * sn + v1 * cs;
                        v0 = y0; v1 = y1;
                    }
                    __half* Ch = (__half*)args.C[proj];
                    if (proj == 2) {
                        size_t tb = ((size_t)(b * NHEADS + hh) * HDIM + dd) * SEQ + n;
                        Ch[tb]       = __float2half_rn(v0);
                        Ch[tb + SEQ] = __float2half_rn(v1);
                    } else {
                        size_t base = (((size_t)(b * NHEADS + hh)) * SEQ + n) * HDIM + dd;
                        *(uint32_t*)&Ch[base] = pack_h2(v0 * scl, v1 * scl);
                    }
                } else {
                    float* Cf = (float*)args.C[proj];
                    *(float2*)&Cf[(size_t)r * DMODEL + cg] = make_float2(v0, v1);
                }
            }
        }
    }
}

// ---------------------------------------------------------------------------
// Flash attention: GEMM2(t-1) -> GEMM1(t) -> softmax(t), 3 CTAs/SM.
// pf(t-1) dies before sc(t) is built -> lower register peak -> occupancy 3.
// 4 smem stages. 128 q-rows/CTA, 4 warps (32x64). K [key][dim], V^T [dim][key].
// ---------------------------------------------------------------------------
#define AKV_STG 16384              // K 8KB + V 8KB per stage
#define ATTN_SMEM (4*AKV_STG)

__global__ __launch_bounds__(128, 3)
void attn_f16_kernel(const __half* __restrict__ Q, const __half* __restrict__ Kg,
                     const __half* __restrict__ Vg, __half* __restrict__ O)
{
    extern __shared__ __align__(128) uint8_t smem[];
    const uint32_t sb = smem_u32(smem);

    const int tid  = threadIdx.x;
    const int warp = tid >> 5;
    const int lane = tid & 31;
    const int qb = blockIdx.x & 15;
    const int bh = blockIdx.x >> 4;

    const int q = lane & 3;
    const int s = lane >> 2;

    // Q fragments
    const uint32_t* qw = (const uint32_t*)(Q + ((size_t)bh * SEQ + qb * 128) * HDIM);
    uint32_t qf[2][4][4];
#pragma unroll
    for (int mt = 0; mt < 2; mt++) {
        int r = warp * 32 + mt * 16 + s;
#pragma unroll
        for (int ks = 0; ks < 4; ks++) {
            qf[mt][ks][0] = qw[(size_t)r * 32 + ks * 8 + q];
            qf[mt][ks][1] = qw[(size_t)(r + 8) * 32 + ks * 8 + q];
            qf[mt][ks][2] = qw[(size_t)r * 32 + ks * 8 + q + 4];
            qf[mt][ks][3] = qw[(size_t)(r + 8) * 32 + ks * 8 + q + 4];
        }
    }

    float m[2][2];
    float lacc[2][4];
    float o[2][8][4];
    uint32_t pf[2][8][2];          // P(t-1) fragments
#pragma unroll
    for (int mt = 0; mt < 2; mt++) {
        m[mt][0] = -1e30f; m[mt][1] = -1e30f;
#pragma unroll
        for (int rr = 0; rr < 4; rr++) lacc[mt][rr] = 0.f;
#pragma unroll
        for (int nt = 0; nt < 8; nt++)
#pragma unroll
            for (int rr = 0; rr < 4; rr++) o[mt][nt][rr] = 0.f;
    }

    const __half* kbp = Kg + (size_t)bh * SEQ * HDIM;            // [key][dim]
    const __half* vbp = Vg + (size_t)bh * HDIM * SEQ;            // [dim][key]

    const int cc  = tid & 7;
    const int r16 = tid >> 3;

#define ATTN_COPY(kt, stage) do { \
    uint32_t _sK = sb + (stage) * AKV_STG; \
    uint32_t _sV = _sK + 8192; \
    _Pragma("unroll") \
    for (int i = 0; i < 4; i++) { \
        int R = r16 + 16 * i; \
        uint32_t _d = R * 128 + ((cc ^ (R & 7)) << 4); \
        cp_async16(_sK + _d, kbp + (size_t)((kt) + R) * HDIM + cc * 8); \
        cp_async16(_sV + _d, vbp + (size_t)R * SEQ + (kt) + cc * 8); \
    } \
} while (0)

    ATTN_COPY(0, 0);  CP_COMMIT();
    ATTN_COPY(64, 1); CP_COMMIT();

    // ldmatrix B addressing
    const int rlow = lane & 7;
    const int hbit = (lane >> 3) & 1;
    const int qbit = (lane >> 4) & 1;
    uint32_t kSw[4];
#pragma unroll
    for (int ks = 0; ks < 4; ks++)
        kSw[ks] = ((uint32_t)((2 * ks + hbit) ^ rlow)) << 4;
    const uint32_t nRb = (uint32_t)(qbit * 8 + rlow) * 128;

#pragma unroll 1
    for (int t = 0; t < 32; t++) {
        if (t < 31) CP_WAIT_1(); else CP_WAIT_0();
        __syncthreads();
        if (t + 2 < 32) { ATTN_COPY((t + 2) * 64, (t + 2) & 3); CP_COMMIT(); }

        // GEMM2(t-1): O += P(t-1) V(t-1)^T, lacc += P(t-1)·1  (pf dies here)
        if (t > 0) {
            const uint32_t vprev = sb + ((t - 1) & 3) * AKV_STG + 8192;
#pragma unroll
            for (int kbi = 0; kbi < 4; kbi++) {
                uint32_t a0[4] = { pf[0][2*kbi][0], pf[0][2*kbi][1],
                                   pf[0][2*kbi+1][0], pf[0][2*kbi+1][1] };
                uint32_t a1[4] = { pf[1][2*kbi][0], pf[1][2*kbi][1],
                                   pf[1][2*kbi+1][0], pf[1][2*kbi+1][1] };
#pragma unroll
                for (int ntp = 0; ntp < 4; ntp++) {
                    uint32_t bf[4];
                    ldsm_x4(bf, vprev + nRb + ntp * 2048 + kSw[kbi]);
                    mma_f16(o[0][2 * ntp],     a0, bf[0], bf[1]);
                    mma_f16(o[1][2 * ntp],     a1, bf[0], bf[1]);
                    mma_f16(o[0][2 * ntp + 1], a0, bf[2], bf[3]);
                    mma_f16(o[1][2 * ntp + 1], a1, bf[2], bf[3]);
                }
                mma_f16(lacc[0], a0, ONES_H2, ONES_H2);
                mma_f16(lacc[1], a1, ONES_H2, ONES_H2);
            }
        }

        const uint32_t koff = sb + (t & 3) * AKV_STG;

        // GEMM1: S(t) = Q * K(t)^T  (log2-domain logits)
        float sc[2][8][4];
#pragma unroll
        for (int mt = 0; mt < 2; mt++)
#pragma unroll
            for (int nt = 0; nt < 8; nt++)
#pragma unroll
                for (int rr = 0; rr < 4; rr++) sc[mt][nt][rr] = 0.f;

#pragma unroll
        for (int ks = 0; ks < 4; ks++) {
#pragma unroll
            for (int ntp = 0; ntp < 4; ntp++) {
                uint32_t bf[4];
                ldsm_x4(bf, koff + nRb + ntp * 2048 + kSw[ks]);
                mma_f16(sc[0][2 * ntp],     qf[0][ks], bf[0], bf[1]);
                mma_f16(sc[1][2 * ntp],     qf[1][ks], bf[0], bf[1]);
                mma_f16(sc[0][2 * ntp + 1], qf[0][ks], bf[2], bf[3]);
                mma_f16(sc[1][2 * ntp + 1], qf[1][ks], bf[2], bf[3]);
            }
        }

        // softmax(t): new max, pack P(t), rescale O+lacc
#pragma unroll
        for (int mt = 0; mt < 2; mt++) {
            float rm0 = -1e30f, rm1 = -1e30f;
#pragma unroll
            for (int nt = 0; nt < 8; nt++) {
                rm0 = fmaxf(rm0, fmaxf(sc[mt][nt][0], sc[mt][nt][1]));
                rm1 = fmaxf(rm1, fmaxf(sc[mt][nt][2], sc[mt][nt][3]));
            }
            rm0 = fmaxf(rm0, __shfl_xor_sync(0xffffffffu, rm0, 1));
            rm0 = fmaxf(rm0, __shfl_xor_sync(0xffffffffu, rm0, 2));
            rm1 = fmaxf(rm1, __shfl_xor_sync(0xffffffffu, rm1, 1));
            rm1 = fmaxf(rm1, __shfl_xor_sync(0xffffffffu, rm1, 2));

            float mn0 = fmaxf(m[mt][0], rm0), mn1 = fmaxf(m[mt][1], rm1);
            float cr0 = fast_exp2(m[mt][0] - mn0), cr1 = fast_exp2(m[mt][1] - mn1);
            m[mt][0] = mn0; m[mt][1] = mn1;

#pragma unroll
            for (int nt = 0; nt < 8; nt++) {
                pf[mt][nt][0] = h2exp2_u32(pack_h2(sc[mt][nt][0] - mn0, sc[mt][nt][1] - mn0));
                pf[mt][nt][1] = h2exp2_u32(pack_h2(sc[mt][nt][2] - mn1, sc[mt][nt][3] - mn1));
            }

            if (!__all_sync(0xffffffffu, (cr0 == 1.f) && (cr1 == 1.f))) {
                lacc[mt][0] *= cr0;
                lacc[mt][2] *= cr1;
#pragma unroll
                for (int nt = 0; nt < 8; nt++) {
                    o[mt][nt][0] *= cr0; o[mt][nt][1] *= cr0;
                    o[mt][nt][2] *= cr1; o[mt][nt][3] *= cr1;
                }
            }
        }
    }

    // final GEMM2 for P(31) (stage 3 still valid)
    {
        const uint32_t vlast = sb + 3 * AKV_STG + 8192;
#pragma unroll
        for (int kbi = 0; kbi < 4; kbi++) {
            uint32_t a0[4] = { pf[0][2*kbi][0], pf[0][2*kbi][1],
                               pf[0][2*kbi+1][0], pf[0][2*kbi+1][1] };
            uint32_t a1[4] = { pf[1][2*kbi][0], pf[1][2*kbi][1],
                               pf[1][2*kbi+1][0], pf[1][2*kbi+1][1] };
#pragma unroll
            for (int ntp = 0; ntp < 4; ntp++) {
                uint32_t bf[4];
                ldsm_x4(bf, vlast + nRb + ntp * 2048 + kSw[kbi]);
                mma_f16(o[0][2 * ntp],     a0, bf[0], bf[1]);
                mma_f16(o[1][2 * ntp],     a1, bf[0], bf[1]);
                mma_f16(o[0][2 * ntp + 1], a0, bf[2], bf[3]);
                mma_f16(o[1][2 * ntp + 1], a1, bf[2], bf[3]);
            }
            mma_f16(lacc[0], a0, ONES_H2, ONES_H2);
            mma_f16(lacc[1], a1, ONES_H2, ONES_H2);
        }
    }

    // finalize -> O half [B,N,DMODEL]
    int b = bh >> 4, h = bh & 15;
#pragma unroll
    for (int mt = 0; mt < 2; mt++) {
        float inv0 = 1.f / lacc[mt][0], inv1 = 1.f / lacc[mt][2];
        int n0 = qb * 128 + warp * 32 + mt * 16 + s;
        size_t base0 = ((size_t)(b * SEQ + n0)) * DMODEL + h * HDIM;
        size_t base1 = ((size_t)(b * SEQ + n0 + 8)) * DMODEL + h * HDIM;
#pragma unroll
        for (int nt = 0; nt < 8; nt++) {
            int c0 = nt * 8 + 2 * q;
            *(uint32_t*)&O[base0 + c0] = pack_h2(o[mt][nt][0] * inv0, o[mt][nt][1] * inv0);
            *(uint32_t*)&O[base1 + c0] = pack_h2(o[mt][nt][2] * inv1, o[mt][nt][3] * inv1);
        }
    }
}

// ---------------------------------------------------------------------------
extern "C" void kernel_launch(void* const* d_in, const int* in_sizes, int n_in,
                              void* d_out, int out_size)
{
    const float* x    = (const float*)d_in[0];
    const float* qpos = (const float*)d_in[1];
    const float* kpos = (const float*)d_in[2];
    const float* Wq = (const float*)d_in[3];
    const float* bq = (const float*)d_in[4];
    const float* Wk = (const float*)d_in[5];
    const float* bk = (const float*)d_in[6];
    const float* Wv = (const float*)d_in[7];
    const float* bv = (const float*)d_in[8];
    const float* Wo = (const float*)d_in[9];
    const float* bo = (const float*)d_in[10];
    float* out = (float*)d_out;

    __half *pq, *pk, *pv, *po, *pxh, *pwh;
    cudaGetSymbolAddress((void**)&pq, g_q);
    cudaGetSymbolAddress((void**)&pk, g_k);
    cudaGetSymbolAddress((void**)&pv, g_v);
    cudaGetSymbolAddress((void**)&po, g_o);
    cudaGetSymbolAddress((void**)&pxh, g_xh);
    cudaGetSymbolAddress((void**)&pwh, g_wh);

    cudaFuncSetAttribute(gemm_mma_kernel,
                         cudaFuncAttributeMaxDynamicSharedMemorySize, GEMM_SMEM);
    cudaFuncSetAttribute(attn_f16_kernel,
                         cudaFuncAttributeMaxDynamicSharedMemorySize, ATTN_SMEM);

    // one merged pre-convert launch
    CvtArgs ca;
    ca.src[0] = (const float4*)x;
    ca.src[1] = (const float4*)Wq;
    ca.src[2] = (const float4*)Wk;
    ca.src[3] = (const float4*)Wv;
    ca.src[4] = (const float4*)Wo;
    cvt_all_kernel<<<(NX4 + 4 * NW4) / 256, 256>>>(ca, (uint2*)pxh, (uint2*)pwh);

    // fused QKV projection (+rope; q pre-scaled by 0.125*log2e; V transposed)
    GemmArgs qkv;
    qkv.A = pxh;
    qkv.W[0] = pwh; qkv.W[1] = pwh + DMODEL * DMODEL; qkv.W[2] = pwh + 2 * DMODEL * DMODEL;
    qkv.bias[0] = bq; qkv.bias[1] = bk; qkv.bias[2] = bv;
    qkv.C[0] = pq; qkv.C[1] = pk; qkv.C[2] = pv;
    qkv.pos[0] = qpos; qkv.pos[1] = kpos; qkv.pos[2] = nullptr;
    qkv.layout_bhnd = 1;
    gemm_mma_kernel<<<dim3(24, 32), 256, GEMM_SMEM>>>(qkv);

    // attention
    attn_f16_kernel<<<BATCH * NHEADS * (SEQ / 128), 128, ATTN_SMEM>>>(pq, pk, pv, po);

    // output projection
    GemmArgs op;
    op.A = po;
    op.W[0] = op.W[1] = op.W[2] = pwh + 3 * DMODEL * DMODEL;
    op.bias[0] = op.bias[1] = op.bias[2] = bo;
    op.C[0] = op.C[1] = op.C[2] = out;
    op.pos[0] = op.pos[1] = op.pos[2] = nullptr;
    op.layout_bhnd = 0;
    gemm_mma_kernel<<<dim3(8, 32), 256, GEMM_SMEM>>>(op);
}

// round 16
// speedup vs baseline: 1.0438x; 1.0438x over previous
#include <cuda_runtime.h>
#include <cuda_fp16.h>
#include <math.h>
#include <stdint.h>

#define BATCH   2
#define SEQ     2048
#define DMODEL  1024
#define NHEADS  16
#define HDIM    64
#define M_ROWS  (BATCH*SEQ)
#define ROPE_SCALE 0.006135923151542565f      // 2*pi/1024
#define LOG2_1E4_OVER16 0.830482023721841f    // log2(10000)/16
#define QSCALE 0.1803368801111204f            // 0.125 * log2(e)

// Scratch (device globals: allocation-free)
__device__ __half g_q[BATCH*NHEADS*SEQ*HDIM];   // [B,H,N,D] fp16, *0.125*log2e, roped
__device__ __half g_k[BATCH*NHEADS*SEQ*HDIM];   // [B,H,N,D] fp16, roped
__device__ __half g_v[BATCH*NHEADS*HDIM*SEQ];   // [B,H,D,N] fp16 TRANSPOSED
__device__ __half g_o[BATCH*SEQ*DMODEL];        // [B,N,d] fp16
__device__ __half g_xh[M_ROWS*DMODEL];          // x as fp16
__device__ __half g_wh[4*DMODEL*DMODEL];        // Wq,Wk,Wv,Wo as fp16

// ---------------------------------------------------------------------------
// helpers
// ---------------------------------------------------------------------------
__device__ __forceinline__ float fast_exp2(float x) {
    float y;
    asm("ex2.approx.f32 %0, %1;" : "=f"(y) : "f"(x));
    return y;
}
__device__ __forceinline__ uint32_t smem_u32(const void* p) {
    uint32_t a;
    asm("{ .reg .u64 t; cvta.to.shared.u64 t, %1; cvt.u32.u64 %0, t; }"
        : "=r"(a) : "l"(p));
    return a;
}
__device__ __forceinline__ void cp_async16(uint32_t dst, const void* src) {
    asm volatile("cp.async.cg.shared.global [%0], [%1], 16;" :: "r"(dst), "l"(src));
}
#define CP_COMMIT()  asm volatile("cp.async.commit_group;" ::: "memory")
#define CP_WAIT_1()  asm volatile("cp.async.wait_group 1;" ::: "memory")
#define CP_WAIT_0()  asm volatile("cp.async.wait_group 0;" ::: "memory")

__device__ __forceinline__ uint32_t pack_h2(float a, float b) {
    __half2 h = __floats2half2_rn(a, b);
    return *(uint32_t*)&h;
}
__device__ __forceinline__ uint32_t h2exp2_u32(uint32_t x) {
    uint32_t y;
    asm("ex2.approx.f16x2 %0, %1;" : "=r"(y) : "r"(x));
    return y;
}

__device__ __forceinline__ void ldsm_x4(uint32_t* r, uint32_t addr) {
    asm volatile("ldmatrix.sync.aligned.m8n8.x4.shared.b16 {%0,%1,%2,%3}, [%4];"
        : "=r"(r[0]), "=r"(r[1]), "=r"(r[2]), "=r"(r[3]) : "r"(addr));
}

// m16n8k16 fp16 MMA, fp32 accumulate
__device__ __forceinline__ void mma_f16(float c[4], const uint32_t a[4],
                                        uint32_t b0, uint32_t b1)
{
    asm volatile(
        "mma.sync.aligned.m16n8k16.row.col.f32.f16.f16.f32 "
        "{%0,%1,%2,%3}, {%4,%5,%6,%7}, {%8,%9}, {%0,%1,%2,%3};\n"
        : "+f"(c[0]), "+f"(c[1]), "+f"(c[2]), "+f"(c[3])
        : "r"(a[0]), "r"(a[1]), "r"(a[2]), "r"(a[3]), "r"(b0), "r"(b1));
}

#define ONES_H2 0x3C003C00u   // (1.0h, 1.0h)

// ---------------------------------------------------------------------------
// merged fp16 pre-convert
// ---------------------------------------------------------------------------
struct CvtArgs { const float4* src[5]; };
#define NX4 (M_ROWS*DMODEL/4)
#define NW4 (DMODEL*DMODEL/4)

__global__ void cvt_all_kernel(CvtArgs a, uint2* __restrict__ dstX,
                               uint2* __restrict__ dstW)
{
    int i = blockIdx.x * blockDim.x + threadIdx.x;
    float4 v;
    uint2* d;
    if (i < NX4) {
        v = a.src[0][i];
        d = dstX + i;
    } else {
        int j = i - NX4;
        v = a.src[1 + (j >> 18)][j & (NW4 - 1)];
        d = dstW + j;
    }
    *d = make_uint2(pack_h2(v.x, v.y), pack_h2(v.z, v.w));
}

// ---------------------------------------------------------------------------
// fp16 mma GEMM (unchanged): cp.async + ldmatrix, 3-stage pipeline.
// ---------------------------------------------------------------------------
struct GemmArgs {
    const __half* A;
    const __half* W[3];
    const float*  bias[3];
    void*         C[3];
    const float*  pos[3];
    int layout_bhnd;
};

#define G_STG 32768
#define GEMM_SMEM (3*G_STG)

__global__ __launch_bounds__(256, 2)
void gemm_mma_kernel(GemmArgs args)
{
    extern __shared__ __align__(128) uint8_t smem[];
    const uint32_t sb = smem_u32(smem);

    const int tid  = threadIdx.x;
    const int warp = tid >> 5;
    const int lane = tid & 31;
    const int wm = (warp & 1) * 64;
    const int wn = (warp >> 1) * 32;
    const int proj = blockIdx.x >> 3;
    const int bn   = (blockIdx.x & 7) * 128;
    const int bm   = blockIdx.y * 128;

    const __half* A    = args.A;
    const __half* W    = args.W[proj];
    const float*  bias = args.bias[proj];
    const float*  pos  = args.pos[proj];

    const int cc = tid & 7;
    const int cr = tid >> 3;
    const __half* gA = A + (size_t)(bm + cr) * DMODEL + cc * 8;
    const __half* gB = W + (size_t)(bn + cr) * DMODEL + cc * 8;
    uint32_t cdst[4];
#pragma unroll
    for (int i = 0; i < 4; i++) {
        int R = cr + 32 * i;
        cdst[i] = R * 128 + ((cc ^ (R & 7)) << 4);
    }

#define GEMM_COPY(tile, stage) do { \
    uint32_t _sA = sb + (stage) * G_STG; \
    uint32_t _sB = _sA + 16384; \
    const __half* _ga = gA + (size_t)(tile) * 64; \
    const __half* _gb = gB + (size_t)(tile) * 64; \
    _Pragma("unroll") \
    for (int i = 0; i < 4; i++) { \
        cp_async16(_sA + cdst[i], _ga + (size_t)i * 32 * DMODEL); \
        cp_async16(_sB + cdst[i], _gb + (size_t)i * 32 * DMODEL); \
    } \
} while (0)

    float acc[4][4][4];
#pragma unroll
    for (int mt = 0; mt < 4; mt++)
#pragma unroll
        for (int nt = 0; nt < 4; nt++)
#pragma unroll
            for (int r = 0; r < 4; r++) acc[mt][nt][r] = 0.f;

    GEMM_COPY(0, 0); CP_COMMIT();
    GEMM_COPY(1, 1); CP_COMMIT();

    const int q = lane & 3;
    const int s = lane >> 2;

    const int rlow = lane & 7;
    const int hbit = (lane >> 3) & 1;
    const int qbit = (lane >> 4) & 1;
    uint32_t aSw[4], bSw[4];
#pragma unroll
    for (int kbi = 0; kbi < 4; kbi++) {
        aSw[kbi] = ((uint32_t)((2 * kbi + qbit) ^ rlow)) << 4;
        bSw[kbi] = ((uint32_t)((2 * kbi + hbit) ^ rlow)) << 4;
    }
    const uint32_t aRb = (uint32_t)(wm + hbit * 8 + rlow) * 128;
    const uint32_t bRb = (uint32_t)(wn + qbit * 8 + rlow) * 128 + 16384;

    int ms = 0, ps = 2;
#pragma unroll 1
    for (int k0 = 0; k0 < 16; k0++) {
        if (k0 < 15) CP_WAIT_1(); else CP_WAIT_0();
        __syncthreads();
        if (k0 + 2 < 16) { GEMM_COPY(k0 + 2, ps); CP_COMMIT(); }

        const uint32_t soff = sb + ms * G_STG;

#pragma unroll
        for (int kbi = 0; kbi < 4; kbi++) {
            uint32_t af[4][4];
#pragma unroll
            for (int mt = 0; mt < 4; mt++)
                ldsm_x4(af[mt], soff + aRb + mt * 2048 + aSw[kbi]);
            uint32_t bf[2][4];
#pragma unroll
            for (int ntp = 0; ntp < 2; ntp++)
                ldsm_x4(bf[ntp], soff + bRb + ntp * 2048 + bSw[kbi]);
#pragma unroll
            for (int nt = 0; nt < 4; nt++) {
                uint32_t b0 = bf[nt >> 1][(nt & 1) * 2];
                uint32_t b1 = bf[nt >> 1][(nt & 1) * 2 + 1];
#pragma unroll
                for (int mt = 0; mt < 4; mt++)
                    mma_f16(acc[mt][nt], af[mt], b0, b1);
            }
        }
        ms = (ms == 2) ? 0 : ms + 1;
        ps = (ps == 2) ? 0 : ps + 1;
    }

    // epilogue
    const float scl = (proj == 0 && args.layout_bhnd) ? QSCALE : 1.0f;
#pragma unroll
    for (int nt = 0; nt < 4; nt++) {
        int cg = bn + wn + nt * 8 + 2 * q;
        float bv0 = bias[cg], bv1 = bias[cg + 1];
        int dd = cg & 63;
        int hh = (cg >> 6) & (NHEADS - 1);
        int ip = (dd & 31) >> 1;
        int plane = (dd >> 5) & 1;
        float invf = fast_exp2(-LOG2_1E4_OVER16 * (float)ip) * ROPE_SCALE;
#pragma unroll
        for (int mt = 0; mt < 4; mt++) {
            int r0 = bm + wm + mt * 16 + s;
#pragma unroll
            for (int rr = 0; rr < 2; rr++) {
                int r = r0 + rr * 8;
                float v0 = acc[mt][nt][rr * 2 + 0] + bv0;
                float v1 = acc[mt][nt][rr * 2 + 1] + bv1;
                if (args.layout_bhnd) {
                    int b = r >> 11, n = r & 2047;
                    if (pos) {
                        float ang = pos[((size_t)(b * SEQ + n)) * 2 + plane] * invf;
                        float sn, cs;
                        __sincosf(ang, &sn, &cs);
                        float y0 = v0 * cs - v1 * sn;
                        float y1 = v0 * sn + v1 * cs;
                        v0 = y0; v1 = y1;
                    }
                    __half* Ch = (__half*)args.C[proj];
                    if (proj == 2) {
                        size_t tb = ((size_t)(b * NHEADS + hh) * HDIM + dd) * SEQ + n;
                        Ch[tb]       = __float2half_rn(v0);
                        Ch[tb + SEQ] = __float2half_rn(v1);
                    } else {
                        size_t base = (((size_t)(b * NHEADS + hh)) * SEQ + n) * HDIM + dd;
                        *(uint32_t*)&Ch[base] = pack_h2(v0 * scl, v1 * scl);
                    }
                } else {
                    float* Cf = (float*)args.C[proj];
                    *(float2*)&Cf[(size_t)r * DMODEL + cg] = make_float2(v0, v1);
                }
            }
        }
    }
}

// ---------------------------------------------------------------------------
// Flash attention: R14 inner loop, but 256 q-rows/CTA with 8 warps sharing
// each K/V tile -> half the CTAs, half the K/V L2 traffic.
// Pingpong: GEMM1(t) -> GEMM2(t-1)+lMMA(t-1) -> softmax(t). 4 smem stages.
// ---------------------------------------------------------------------------
#define AKV_STG 16384              // K 8KB + V 8KB per stage
#define ATTN_SMEM (4*AKV_STG)

__global__ __launch_bounds__(256)
void attn_f16_kernel(const __half* __restrict__ Q, const __half* __restrict__ Kg,
                     const __half* __restrict__ Vg, __half* __restrict__ O)
{
    extern __shared__ __align__(128) uint8_t smem[];
    const uint32_t sb = smem_u32(smem);

    const int tid  = threadIdx.x;
    const int warp = tid >> 5;          // 0..7 (each owns 32 q-rows)
    const int lane = tid & 31;
    const int qb = blockIdx.x & 7;      // 8 q-blocks of 256 per (b,h)
    const int bh = blockIdx.x >> 3;

    const int q = lane & 3;
    const int s = lane >> 2;

    // Q fragments (rows qb*256 + warp*32 + ...)
    const uint32_t* qw = (const uint32_t*)(Q + ((size_t)bh * SEQ + qb * 256) * HDIM);
    uint32_t qf[2][4][4];
#pragma unroll
    for (int mt = 0; mt < 2; mt++) {
        int r = warp * 32 + mt * 16 + s;
#pragma unroll
        for (int ks = 0; ks < 4; ks++) {
            qf[mt][ks][0] = qw[(size_t)r * 32 + ks * 8 + q];
            qf[mt][ks][1] = qw[(size_t)(r + 8) * 32 + ks * 8 + q];
            qf[mt][ks][2] = qw[(size_t)r * 32 + ks * 8 + q + 4];
            qf[mt][ks][3] = qw[(size_t)(r + 8) * 32 + ks * 8 + q + 4];
        }
    }

    float m[2][2];
    float lacc[2][4];
    float o[2][8][4];
    uint32_t pf[2][8][2];          // P(t-1) fragments
#pragma unroll
    for (int mt = 0; mt < 2; mt++) {
        m[mt][0] = -1e30f; m[mt][1] = -1e30f;
#pragma unroll
        for (int rr = 0; rr < 4; rr++) lacc[mt][rr] = 0.f;
#pragma unroll
        for (int nt = 0; nt < 8; nt++)
#pragma unroll
            for (int rr = 0; rr < 4; rr++) o[mt][nt][rr] = 0.f;
    }

    const __half* kbp = Kg + (size_t)bh * SEQ * HDIM;            // [key][dim]
    const __half* vbp = Vg + (size_t)bh * HDIM * SEQ;            // [dim][key]

    // copy mapping for 256 threads: rows r32 and r32+32, chunk cc
    const int cc  = tid & 7;
    const int r32 = tid >> 3;           // 0..31

#define ATTN_COPY(kt, stage) do { \
    uint32_t _sK = sb + (stage) * AKV_STG; \
    uint32_t _sV = _sK + 8192; \
    _Pragma("unroll") \
    for (int i = 0; i < 2; i++) { \
        int R = r32 + 32 * i; \
        uint32_t _d = R * 128 + ((cc ^ (R & 7)) << 4); \
        cp_async16(_sK + _d, kbp + (size_t)((kt) + R) * HDIM + cc * 8); \
        cp_async16(_sV + _d, vbp + (size_t)R * SEQ + (kt) + cc * 8); \
    } \
} while (0)

    ATTN_COPY(0, 0);  CP_COMMIT();
    ATTN_COPY(64, 1); CP_COMMIT();

    // ldmatrix B addressing
    const int rlow = lane & 7;
    const int hbit = (lane >> 3) & 1;
    const int qbit = (lane >> 4) & 1;
    uint32_t kSw[4];
#pragma unroll
    for (int ks = 0; ks < 4; ks++)
        kSw[ks] = ((uint32_t)((2 * ks + hbit) ^ rlow)) << 4;
    const uint32_t nRb = (uint32_t)(qbit * 8 + rlow) * 128;

#pragma unroll 1
    for (int t = 0; t < 32; t++) {
        if (t < 31) CP_WAIT_1(); else CP_WAIT_0();
        __syncthreads();
        if (t + 2 < 32) { ATTN_COPY((t + 2) * 64, (t + 2) & 3); CP_COMMIT(); }

        const uint32_t koff = sb + (t & 3) * AKV_STG;

        // GEMM1: S(t) = Q * K(t)^T  (log2-domain logits)
        float sc[2][8][4];
#pragma unroll
        for (int mt = 0; mt < 2; mt++)
#pragma unroll
            for (int nt = 0; nt < 8; nt++)
#pragma unroll
                for (int rr = 0; rr < 4; rr++) sc[mt][nt][rr] = 0.f;

#pragma unroll
        for (int ks = 0; ks < 4; ks++) {
#pragma unroll
            for (int ntp = 0; ntp < 4; ntp++) {
                uint32_t bf[4];
                ldsm_x4(bf, koff + nRb + ntp * 2048 + kSw[ks]);
                mma_f16(sc[0][2 * ntp],     qf[0][ks], bf[0], bf[1]);
                mma_f16(sc[1][2 * ntp],     qf[1][ks], bf[0], bf[1]);
                mma_f16(sc[0][2 * ntp + 1], qf[0][ks], bf[2], bf[3]);
                mma_f16(sc[1][2 * ntp + 1], qf[1][ks], bf[2], bf[3]);
            }
        }

        // deferred GEMM2 + l-MMA: O += P(t-1) V(t-1)^T, lacc += P(t-1)·1
        if (t > 0) {
            const uint32_t vprev = sb + ((t - 1) & 3) * AKV_STG + 8192;
#pragma unroll
            for (int kbi = 0; kbi < 4; kbi++) {
                uint32_t a0[4] = { pf[0][2*kbi][0], pf[0][2*kbi][1],
                                   pf[0][2*kbi+1][0], pf[0][2*kbi+1][1] };
                uint32_t a1[4] = { pf[1][2*kbi][0], pf[1][2*kbi][1],
                                   pf[1][2*kbi+1][0], pf[1][2*kbi+1][1] };
#pragma unroll
                for (int ntp = 0; ntp < 4; ntp++) {
                    uint32_t bf[4];
                    ldsm_x4(bf, vprev + nRb + ntp * 2048 + kSw[kbi]);
                    mma_f16(o[0][2 * ntp],     a0, bf[0], bf[1]);
                    mma_f16(o[1][2 * ntp],     a1, bf[0], bf[1]);
                    mma_f16(o[0][2 * ntp + 1], a0, bf[2], bf[3]);
                    mma_f16(o[1][2 * ntp + 1], a1, bf[2], bf[3]);
                }
                mma_f16(lacc[0], a0, ONES_H2, ONES_H2);
                mma_f16(lacc[1], a1, ONES_H2, ONES_H2);
            }
        }

        // softmax(t): new max, rescale O+lacc, pack P(t)
#pragma unroll
        for (int mt = 0; mt < 2; mt++) {
            float rm0 = -1e30f, rm1 = -1e30f;
#pragma unroll
            for (int nt = 0; nt < 8; nt++) {
                rm0 = fmaxf(rm0, fmaxf(sc[mt][nt][0], sc[mt][nt][1]));
                rm1 = fmaxf(rm1, fmaxf(sc[mt][nt][2], sc[mt][nt][3]));
            }
            rm0 = fmaxf(rm0, __shfl_xor_sync(0xffffffffu, rm0, 1));
            rm0 = fmaxf(rm0, __shfl_xor_sync(0xffffffffu, rm0, 2));
            rm1 = fmaxf(rm1, __shfl_xor_sync(0xffffffffu, rm1, 1));
            rm1 = fmaxf(rm1, __shfl_xor_sync(0xffffffffu, rm1, 2));

            float mn0 = fmaxf(m[mt][0], rm0), mn1 = fmaxf(m[mt][1], rm1);
            float cr0 = fast_exp2(m[mt][0] - mn0), cr1 = fast_exp2(m[mt][1] - mn1);
            m[mt][0] = mn0; m[mt][1] = mn1;

#pragma unroll
            for (int nt = 0; nt < 8; nt++) {
                pf[mt][nt][0] = h2exp2_u32(pack_h2(sc[mt][nt][0] - mn0, sc[mt][nt][1] - mn0));
                pf[mt][nt][1] = h2exp2_u32(pack_h2(sc[mt][nt][2] - mn1, sc[mt][nt][3] - mn1));
            }

            if (!__all_sync(0xffffffffu, (cr0 == 1.f) && (cr1 == 1.f))) {
                lacc[mt][0] *= cr0;
                lacc[mt][2] *= cr1;
#pragma unroll
                for (int nt = 0; nt < 8; nt++) {
                    o[mt][nt][0] *= cr0; o[mt][nt][1] *= cr0;
                    o[mt][nt][2] *= cr1; o[mt][nt][3] *= cr1;
                }
            }
        }
    }

    // final deferred GEMM2 + l-MMA for P(31) (stage 3 still valid)
    {
        const uint32_t vlast = sb + 3 * AKV_STG + 8192;
#pragma unroll
        for (int kbi = 0; kbi < 4; kbi++) {
            uint32_t a0[4] = { pf[0][2*kbi][0], pf[0][2*kbi][1],
                               pf[0][2*kbi+1][0], pf[0][2*kbi+1][1] };
            uint32_t a1[4] = { pf[1][2*kbi][0], pf[1][2*kbi][1],
                               pf[1][2*kbi+1][0], pf[1][2*kbi+1][1] };
#pragma unroll
            for (int ntp = 0; ntp < 4; ntp++) {
                uint32_t bf[4];
                ldsm_x4(bf, vlast + nRb + ntp * 2048 + kSw[kbi]);
                mma_f16(o[0][2 * ntp],     a0, bf[0], bf[1]);
                mma_f16(o[1][2 * ntp],     a1, bf[0], bf[1]);
                mma_f16(o[0][2 * ntp + 1], a0, bf[2], bf[3]);
                mma_f16(o[1][2 * ntp + 1], a1, bf[2], bf[3]);
            }
            mma_f16(lacc[0], a0, ONES_H2, ONES_H2);
            mma_f16(lacc[1], a1, ONES_H2, ONES_H2);
        }
    }

    // finalize -> O half [B,N,DMODEL]
    int b = bh >> 4, h = bh & 15;
#pragma unroll
    for (int mt = 0; mt < 2; mt++) {
        float inv0 = 1.f / lacc[mt][0], inv1 = 1.f / lacc[mt][2];
        int n0 = qb * 256 + warp * 32 + mt * 16 + s;
        size_t base0 = ((size_t)(b * SEQ + n0)) * DMODEL + h * HDIM;
        size_t base1 = ((size_t)(b * SEQ + n0 + 8)) * DMODEL + h * HDIM;
#pragma unroll
        for (int nt = 0; nt < 8; nt++) {
            int c0 = nt * 8 + 2 * q;
            *(uint32_t*)&O[base0 + c0] = pack_h2(o[mt][nt][0] * inv0, o[mt][nt][1] * inv0);
            *(uint32_t*)&O[base1 + c0] = pack_h2(o[mt][nt][2] * inv1, o[mt][nt][3] * inv1);
        }
    }
}

// ---------------------------------------------------------------------------
extern "C" void kernel_launch(void* const* d_in, const int* in_sizes, int n_in,
                              void* d_out, int out_size)
{
    const float* x    = (const float*)d_in[0];
    const float* qpos = (const float*)d_in[1];
    const float* kpos = (const float*)d_in[2];
    const float* Wq = (const float*)d_in[3];
    const float* bq = (const float*)d_in[4];
    const float* Wk = (const float*)d_in[5];
    const float* bk = (const float*)d_in[6];
    const float* Wv = (const float*)d_in[7];
    const float* bv = (const float*)d_in[8];
    const float* Wo = (const float*)d_in[9];
    const float* bo = (const float*)d_in[10];
    float* out = (float*)d_out;

    __half *pq, *pk, *pv, *po, *pxh, *pwh;
    cudaGetSymbolAddress((void**)&pq, g_q);
    cudaGetSymbolAddress((void**)&pk, g_k);
    cudaGetSymbolAddress((void**)&pv, g_v);
    cudaGetSymbolAddress((void**)&po, g_o);
    cudaGetSymbolAddress((void**)&pxh, g_xh);
    cudaGetSymbolAddress((void**)&pwh, g_wh);

    cudaFuncSetAttribute(gemm_mma_kernel,
                         cudaFuncAttributeMaxDynamicSharedMemorySize, GEMM_SMEM);
    cudaFuncSetAttribute(attn_f16_kernel,
                         cudaFuncAttributeMaxDynamicSharedMemorySize, ATTN_SMEM);

    // one merged pre-convert launch
    CvtArgs ca;
    ca.src[0] = (const float4*)x;
    ca.src[1] = (const float4*)Wq;
    ca.src[2] = (const float4*)Wk;
    ca.src[3] = (const float4*)Wv;
    ca.src[4] = (const float4*)Wo;
    cvt_all_kernel<<<(NX4 + 4 * NW4) / 256, 256>>>(ca, (uint2*)pxh, (uint2*)pwh);

    // fused QKV projection (+rope; q pre-scaled by 0.125*log2e; V transposed)
    GemmArgs qkv;
    qkv.A = pxh;
    qkv.W[0] = pwh; qkv.W[1] = pwh + DMODEL * DMODEL; qkv.W[2] = pwh + 2 * DMODEL * DMODEL;
    qkv.bias[0] = bq; qkv.bias[1] = bk; qkv.bias[2] = bv;
    qkv.C[0] = pq; qkv.C[1] = pk; qkv.C[2] = pv;
    qkv.pos[0] = qpos; qkv.pos[1] = kpos; qkv.pos[2] = nullptr;
    qkv.layout_bhnd = 1;
    gemm_mma_kernel<<<dim3(24, 32), 256, GEMM_SMEM>>>(qkv);

    // attention: 256 q-rows per CTA, 8 warps
    attn_f16_kernel<<<BATCH * NHEADS * (SEQ / 256), 256, ATTN_SMEM>>>(pq, pk, pv, po);

    // output projection
    GemmArgs op;
    op.A = po;
    op.W[0] = op.W[1] = op.W[2] = pwh + 3 * DMODEL * DMODEL;
    op.bias[0] = op.bias[1] = op.bias[2] = bo;
    op.C[0] = op.C[1] = op.C[2] = out;
    op.pos[0] = op.pos[1] = op.pos[2] = nullptr;
    op.layout_bhnd = 0;
    gemm_mma_kernel<<<dim3(8, 32), 256, GEMM_SMEM>>>(op);
}

// round 17
// speedup vs baseline: 1.1003x; 1.0541x over previous
#include <cuda_runtime.h>
#include <cuda_fp16.h>
#include <math.h>
#include <stdint.h>

#define BATCH   2
#define SEQ     2048
#define DMODEL  1024
#define NHEADS  16
#define HDIM    64
#define M_ROWS  (BATCH*SEQ)
#define ROPE_SCALE 0.006135923151542565f      // 2*pi/1024
#define LOG2_1E4_OVER16 0.830482023721841f    // log2(10000)/16
#define QSCALE 0.1803368801111204f            // 0.125 * log2(e)

// Scratch (device globals: allocation-free)
__device__ __half g_q[BATCH*NHEADS*SEQ*HDIM];   // [B,H,N,D] fp16, *0.125*log2e, roped
__device__ __half g_k[BATCH*NHEADS*SEQ*HDIM];   // [B,H,N,D] fp16, roped
__device__ __half g_v[BATCH*NHEADS*HDIM*SEQ];   // [B,H,D,N] fp16 TRANSPOSED
__device__ __half g_o[BATCH*SEQ*DMODEL];        // [B,N,d] fp16
__device__ __half g_xh[M_ROWS*DMODEL];          // x as fp16
__device__ __half g_wh[4*DMODEL*DMODEL];        // Wq,Wk,Wv,Wo as fp16

// ---------------------------------------------------------------------------
// helpers
// ---------------------------------------------------------------------------
__device__ __forceinline__ float fast_exp2(float x) {
    float y;
    asm("ex2.approx.f32 %0, %1;" : "=f"(y) : "f"(x));
    return y;
}
__device__ __forceinline__ uint32_t smem_u32(const void* p) {
    uint32_t a;
    asm("{ .reg .u64 t; cvta.to.shared.u64 t, %1; cvt.u32.u64 %0, t; }"
        : "=r"(a) : "l"(p));
    return a;
}
__device__ __forceinline__ void cp_async16(uint32_t dst, const void* src) {
    asm volatile("cp.async.cg.shared.global [%0], [%1], 16;" :: "r"(dst), "l"(src));
}
#define CP_COMMIT()  asm volatile("cp.async.commit_group;" ::: "memory")
#define CP_WAIT_1()  asm volatile("cp.async.wait_group 1;" ::: "memory")
#define CP_WAIT_0()  asm volatile("cp.async.wait_group 0;" ::: "memory")

__device__ __forceinline__ uint32_t pack_h2(float a, float b) {
    __half2 h = __floats2half2_rn(a, b);
    return *(uint32_t*)&h;
}
__device__ __forceinline__ uint32_t h2exp2_u32(uint32_t x) {
    uint32_t y;
    asm("ex2.approx.f16x2 %0, %1;" : "=r"(y) : "r"(x));
    return y;
}

__device__ __forceinline__ void ldsm_x4(uint32_t* r, uint32_t addr) {
    asm volatile("ldmatrix.sync.aligned.m8n8.x4.shared.b16 {%0,%1,%2,%3}, [%4];"
        : "=r"(r[0]), "=r"(r[1]), "=r"(r[2]), "=r"(r[3]) : "r"(addr));
}

// m16n8k16 fp16 MMA, fp32 accumulate
__device__ __forceinline__ void mma_f16(float c[4], const uint32_t a[4],
                                        uint32_t b0, uint32_t b1)
{
    asm volatile(
        "mma.sync.aligned.m16n8k16.row.col.f32.f16.f16.f32 "
        "{%0,%1,%2,%3}, {%4,%5,%6,%7}, {%8,%9}, {%0,%1,%2,%3};\n"
        : "+f"(c[0]), "+f"(c[1]), "+f"(c[2]), "+f"(c[3])
        : "r"(a[0]), "r"(a[1]), "r"(a[2]), "r"(a[3]), "r"(b0), "r"(b1));
}

#define ONES_H2 0x3C003C00u   // (1.0h, 1.0h)

// ---------------------------------------------------------------------------
// merged fp16 pre-convert
// ---------------------------------------------------------------------------
struct CvtArgs { const float4* src[5]; };
#define NX4 (M_ROWS*DMODEL/4)
#define NW4 (DMODEL*DMODEL/4)

__global__ void cvt_all_kernel(CvtArgs a, uint2* __restrict__ dstX,
                               uint2* __restrict__ dstW)
{
    int i = blockIdx.x * blockDim.x + threadIdx.x;
    float4 v;
    uint2* d;
    if (i < NX4) {
        v = a.src[0][i];
        d = dstX + i;
    } else {
        int j = i - NX4;
        v = a.src[1 + (j >> 18)][j & (NW4 - 1)];
        d = dstW + j;
    }
    *d = make_uint2(pack_h2(v.x, v.y), pack_h2(v.z, v.w));
}

// ---------------------------------------------------------------------------
// fp16 mma GEMM: 128 threads, 4 warps (2x2), warp tile 64x64.
// Crossbar traffic per 32KB tile: A*2 + B*2 = 64KB (was 96KB with 8 warps).
// cp.async + ldmatrix, 3-stage pipeline. CTA tile 128x128, BK=64 halves.
// ---------------------------------------------------------------------------
struct GemmArgs {
    const __half* A;
    const __half* W[3];
    const float*  bias[3];
    void*         C[3];
    const float*  pos[3];
    int layout_bhnd;
};

#define G_STG 32768
#define GEMM_SMEM (3*G_STG)

__global__ __launch_bounds__(128, 2)
void gemm_mma_kernel(GemmArgs args)
{
    extern __shared__ __align__(128) uint8_t smem[];
    const uint32_t sb = smem_u32(smem);

    const int tid  = threadIdx.x;
    const int warp = tid >> 5;          // 0..3
    const int lane = tid & 31;
    const int wm = (warp & 1) * 64;
    const int wn = (warp >> 1) * 64;
    const int proj = blockIdx.x >> 3;
    const int bn   = (blockIdx.x & 7) * 128;
    const int bm   = blockIdx.y * 128;

    const __half* A    = args.A;
    const __half* W    = args.W[proj];
    const float*  bias = args.bias[proj];
    const float*  pos  = args.pos[proj];

    // cp.async mapping: 128 threads -> rows cr+16i (i<8), 16B chunk cc
    const int cc = tid & 7;
    const int cr = tid >> 3;            // 0..15
    const __half* gA = A + (size_t)(bm + cr) * DMODEL + cc * 8;
    const __half* gB = W + (size_t)(bn + cr) * DMODEL + cc * 8;
    uint32_t cdst[8];
#pragma unroll
    for (int i = 0; i < 8; i++) {
        int R = cr + 16 * i;
        cdst[i] = R * 128 + ((cc ^ (R & 7)) << 4);
    }

#define GEMM_COPY(tile, stage) do { \
    uint32_t _sA = sb + (stage) * G_STG; \
    uint32_t _sB = _sA + 16384; \
    const __half* _ga = gA + (size_t)(tile) * 64; \
    const __half* _gb = gB + (size_t)(tile) * 64; \
    _Pragma("unroll") \
    for (int i = 0; i < 8; i++) { \
        cp_async16(_sA + cdst[i], _ga + (size_t)i * 16 * DMODEL); \
        cp_async16(_sB + cdst[i], _gb + (size_t)i * 16 * DMODEL); \
    } \
} while (0)

    float acc[4][8][4];
#pragma unroll
    for (int mt = 0; mt < 4; mt++)
#pragma unroll
        for (int nt = 0; nt < 8; nt++)
#pragma unroll
            for (int r = 0; r < 4; r++) acc[mt][nt][r] = 0.f;

    GEMM_COPY(0, 0); CP_COMMIT();
    GEMM_COPY(1, 1); CP_COMMIT();

    const int q = lane & 3;
    const int s = lane >> 2;

    const int rlow = lane & 7;
    const int hbit = (lane >> 3) & 1;
    const int qbit = (lane >> 4) & 1;
    uint32_t aSw[4], bSw[4];
#pragma unroll
    for (int kbi = 0; kbi < 4; kbi++) {
        aSw[kbi] = ((uint32_t)((2 * kbi + qbit) ^ rlow)) << 4;
        bSw[kbi] = ((uint32_t)((2 * kbi + hbit) ^ rlow)) << 4;
    }
    const uint32_t aRb = (uint32_t)(wm + hbit * 8 + rlow) * 128;
    const uint32_t bRb = (uint32_t)(wn + qbit * 8 + rlow) * 128 + 16384;

    int ms = 0, ps = 2;
#pragma unroll 1
    for (int k0 = 0; k0 < 16; k0++) {
        if (k0 < 15) CP_WAIT_1(); else CP_WAIT_0();
        __syncthreads();
        if (k0 + 2 < 16) { GEMM_COPY(k0 + 2, ps); CP_COMMIT(); }

        const uint32_t soff = sb + ms * G_STG;

#pragma unroll
        for (int kbi = 0; kbi < 4; kbi++) {
            uint32_t af[4][4];
#pragma unroll
            for (int mt = 0; mt < 4; mt++)
                ldsm_x4(af[mt], soff + aRb + mt * 2048 + aSw[kbi]);
#pragma unroll
            for (int ntp = 0; ntp < 4; ntp++) {
                uint32_t bf[4];
                ldsm_x4(bf, soff + bRb + ntp * 2048 + bSw[kbi]);
#pragma unroll
                for (int mt = 0; mt < 4; mt++)
                    mma_f16(acc[mt][2 * ntp], af[mt], bf[0], bf[1]);
#pragma unroll
                for (int mt = 0; mt < 4; mt++)
                    mma_f16(acc[mt][2 * ntp + 1], af[mt], bf[2], bf[3]);
            }
        }
        ms = (ms == 2) ? 0 : ms + 1;
        ps = (ps == 2) ? 0 : ps + 1;
    }

    // epilogue
    const float scl = (proj == 0 && args.layout_bhnd) ? QSCALE : 1.0f;
#pragma unroll
    for (int nt = 0; nt < 8; nt++) {
        int cg = bn + wn + nt * 8 + 2 * q;
        float bv0 = bias[cg], bv1 = bias[cg + 1];
        int dd = cg & 63;
        int hh = (cg >> 6) & (NHEADS - 1);
        int ip = (dd & 31) >> 1;
        int plane = (dd >> 5) & 1;
        float invf = fast_exp2(-LOG2_1E4_OVER16 * (float)ip) * ROPE_SCALE;
#pragma unroll
        for (int mt = 0; mt < 4; mt++) {
            int r0 = bm + wm + mt * 16 + s;
#pragma unroll
            for (int rr = 0; rr < 2; rr++) {
                int r = r0 + rr * 8;
                float v0 = acc[mt][nt][rr * 2 + 0] + bv0;
                float v1 = acc[mt][nt][rr * 2 + 1] + bv1;
                if (args.layout_bhnd) {
                    int b = r >> 11, n = r & 2047;
                    if (pos) {
                        float ang = pos[((size_t)(b * SEQ + n)) * 2 + plane] * invf;
                        float sn, cs;
                        __sincosf(ang, &sn, &cs);
                        float y0 = v0 * cs - v1 * sn;
                        float y1 = v0 * sn + v1 * cs;
                        v0 = y0; v1 = y1;
                    }
                    __half* Ch = (__half*)args.C[proj];
                    if (proj == 2) {
                        size_t tb = ((size_t)(b * NHEADS + hh) * HDIM + dd) * SEQ + n;
                        Ch[tb]       = __float2half_rn(v0);
                        Ch[tb + SEQ] = __float2half_rn(v1);
                    } else {
                        size_t base = (((size_t)(b * NHEADS + hh)) * SEQ + n) * HDIM + dd;
                        *(uint32_t*)&Ch[base] = pack_h2(v0 * scl, v1 * scl);
                    }
                } else {
                    float* Cf = (float*)args.C[proj];
                    *(float2*)&Cf[(size_t)r * DMODEL + cg] = make_float2(v0, v1);
                }
            }
        }
    }
}

// ---------------------------------------------------------------------------
// Flash attention (R14 exact): deferred-PV pingpong + MMA l-sums.
// GEMM1(t) -> GEMM2(t-1)+lMMA(t-1) -> softmax(t). 4 smem stages.
// 128 q-rows/CTA, 4 warps (32x64). K [key64][dim64], V^T [dim64][key64].
// ---------------------------------------------------------------------------
#define AKV_STG 16384              // K 8KB + V 8KB per stage
#define ATTN_SMEM (4*AKV_STG)

__global__ __launch_bounds__(128)
void attn_f16_kernel(const __half* __restrict__ Q, const __half* __restrict__ Kg,
                     const __half* __restrict__ Vg, __half* __restrict__ O)
{
    extern __shared__ __align__(128) uint8_t smem[];
    const uint32_t sb = smem_u32(smem);

    const int tid  = threadIdx.x;
    const int warp = tid >> 5;
    const int lane = tid & 31;
    const int qb = blockIdx.x & 15;
    const int bh = blockIdx.x >> 4;

    const int q = lane & 3;
    const int s = lane >> 2;

    // Q fragments
    const uint32_t* qw = (const uint32_t*)(Q + ((size_t)bh * SEQ + qb * 128) * HDIM);
    uint32_t qf[2][4][4];
#pragma unroll
    for (int mt = 0; mt < 2; mt++) {
        int r = warp * 32 + mt * 16 + s;
#pragma unroll
        for (int ks = 0; ks < 4; ks++) {
            qf[mt][ks][0] = qw[(size_t)r * 32 + ks * 8 + q];
            qf[mt][ks][1] = qw[(size_t)(r + 8) * 32 + ks * 8 + q];
            qf[mt][ks][2] = qw[(size_t)r * 32 + ks * 8 + q + 4];
            qf[mt][ks][3] = qw[(size_t)(r + 8) * 32 + ks * 8 + q + 4];
        }
    }

    float m[2][2];
    float lacc[2][4];
    float o[2][8][4];
    uint32_t pf[2][8][2];          // P(t-1) fragments
#pragma unroll
    for (int mt = 0; mt < 2; mt++) {
        m[mt][0] = -1e30f; m[mt][1] = -1e30f;
#pragma unroll
        for (int rr = 0; rr < 4; rr++) lacc[mt][rr] = 0.f;
#pragma unroll
        for (int nt = 0; nt < 8; nt++)
#pragma unroll
            for (int rr = 0; rr < 4; rr++) o[mt][nt][rr] = 0.f;
    }

    const __half* kbp = Kg + (size_t)bh * SEQ * HDIM;            // [key][dim]
    const __half* vbp = Vg + (size_t)bh * HDIM * SEQ;            // [dim][key]

    const int cc  = tid & 7;
    const int r16 = tid >> 3;

#define ATTN_COPY(kt, stage) do { \
    uint32_t _sK = sb + (stage) * AKV_STG; \
    uint32_t _sV = _sK + 8192; \
    _Pragma("unroll") \
    for (int i = 0; i < 4; i++) { \
        int R = r16 + 16 * i; \
        uint32_t _d = R * 128 + ((cc ^ (R & 7)) << 4); \
        cp_async16(_sK + _d, kbp + (size_t)((kt) + R) * HDIM + cc * 8); \
        cp_async16(_sV + _d, vbp + (size_t)R * SEQ + (kt) + cc * 8); \
    } \
} while (0)

    ATTN_COPY(0, 0);  CP_COMMIT();
    ATTN_COPY(64, 1); CP_COMMIT();

    // ldmatrix B addressing
    const int rlow = lane & 7;
    const int hbit = (lane >> 3) & 1;
    const int qbit = (lane >> 4) & 1;
    uint32_t kSw[4];
#pragma unroll
    for (int ks = 0; ks < 4; ks++)
        kSw[ks] = ((uint32_t)((2 * ks + hbit) ^ rlow)) << 4;
    const uint32_t nRb = (uint32_t)(qbit * 8 + rlow) * 128;

#pragma unroll 1
    for (int t = 0; t < 32; t++) {
        if (t < 31) CP_WAIT_1(); else CP_WAIT_0();
        __syncthreads();
        if (t + 2 < 32) { ATTN_COPY((t + 2) * 64, (t + 2) & 3); CP_COMMIT(); }

        const uint32_t koff = sb + (t & 3) * AKV_STG;

        // GEMM1: S(t) = Q * K(t)^T  (log2-domain logits)
        float sc[2][8][4];
#pragma unroll
        for (int mt = 0; mt < 2; mt++)
#pragma unroll
            for (int nt = 0; nt < 8; nt++)
#pragma unroll
                for (int rr = 0; rr < 4; rr++) sc[mt][nt][rr] = 0.f;

#pragma unroll
        for (int ks = 0; ks < 4; ks++) {
#pragma unroll
            for (int ntp = 0; ntp < 4; ntp++) {
                uint32_t bf[4];
                ldsm_x4(bf, koff + nRb + ntp * 2048 + kSw[ks]);
                mma_f16(sc[0][2 * ntp],     qf[0][ks], bf[0], bf[1]);
                mma_f16(sc[1][2 * ntp],     qf[1][ks], bf[0], bf[1]);
                mma_f16(sc[0][2 * ntp + 1], qf[0][ks], bf[2], bf[3]);
                mma_f16(sc[1][2 * ntp + 1], qf[1][ks], bf[2], bf[3]);
            }
        }

        // deferred GEMM2 + l-MMA: O += P(t-1) V(t-1)^T, lacc += P(t-1)·1
        if (t > 0) {
            const uint32_t vprev = sb + ((t - 1) & 3) * AKV_STG + 8192;
#pragma unroll
            for (int kbi = 0; kbi < 4; kbi++) {
                uint32_t a0[4] = { pf[0][2*kbi][0], pf[0][2*kbi][1],
                                   pf[0][2*kbi+1][0], pf[0][2*kbi+1][1] };
                uint32_t a1[4] = { pf[1][2*kbi][0], pf[1][2*kbi][1],
                                   pf[1][2*kbi+1][0], pf[1][2*kbi+1][1] };
#pragma unroll
                for (int ntp = 0; ntp < 4; ntp++) {
                    uint32_t bf[4];
                    ldsm_x4(bf, vprev + nRb + ntp * 2048 + kSw[kbi]);
                    mma_f16(o[0][2 * ntp],     a0, bf[0], bf[1]);
                    mma_f16(o[1][2 * ntp],     a1, bf[0], bf[1]);
                    mma_f16(o[0][2 * ntp + 1], a0, bf[2], bf[3]);
                    mma_f16(o[1][2 * ntp + 1], a1, bf[2], bf[3]);
                }
                mma_f16(lacc[0], a0, ONES_H2, ONES_H2);
                mma_f16(lacc[1], a1, ONES_H2, ONES_H2);
            }
        }

        // softmax(t): new max, rescale O+lacc, pack P(t)
#pragma unroll
        for (int mt = 0; mt < 2; mt++) {
            float rm0 = -1e30f, rm1 = -1e30f;
#pragma unroll
            for (int nt = 0; nt < 8; nt++) {
                rm0 = fmaxf(rm0, fmaxf(sc[mt][nt][0], sc[mt][nt][1]));
                rm1 = fmaxf(rm1, fmaxf(sc[mt][nt][2], sc[mt][nt][3]));
            }
            rm0 = fmaxf(rm0, __shfl_xor_sync(0xffffffffu, rm0, 1));
            rm0 = fmaxf(rm0, __shfl_xor_sync(0xffffffffu, rm0, 2));
            rm1 = fmaxf(rm1, __shfl_xor_sync(0xffffffffu, rm1, 1));
            rm1 = fmaxf(rm1, __shfl_xor_sync(0xffffffffu, rm1, 2));

            float mn0 = fmaxf(m[mt][0], rm0), mn1 = fmaxf(m[mt][1], rm1);
            float cr0 = fast_exp2(m[mt][0] - mn0), cr1 = fast_exp2(m[mt][1] - mn1);
            m[mt][0] = mn0; m[mt][1] = mn1;

#pragma unroll
            for (int nt = 0; nt < 8; nt++) {
                pf[mt][nt][0] = h2exp2_u32(pack_h2(sc[mt][nt][0] - mn0, sc[mt][nt][1] - mn0));
                pf[mt][nt][1] = h2exp2_u32(pack_h2(sc[mt][nt][2] - mn1, sc[mt][nt][3] - mn1));
            }

            if (!__all_sync(0xffffffffu, (cr0 == 1.f) && (cr1 == 1.f))) {
                lacc[mt][0] *= cr0;
                lacc[mt][2] *= cr1;
#pragma unroll
                for (int nt = 0; nt < 8; nt++) {
                    o[mt][nt][0] *= cr0; o[mt][nt][1] *= cr0;
                    o[mt][nt][2] *= cr1; o[mt][nt][3] *= cr1;
                }
            }
        }
    }

    // final deferred GEMM2 + l-MMA for P(31) (stage 3 still valid)
    {
        const uint32_t vlast = sb + 3 * AKV_STG + 8192;
#pragma unroll
        for (int kbi = 0; kbi < 4; kbi++) {
            uint32_t a0[4] = { pf[0][2*kbi][0], pf[0][2*kbi][1],
                               pf[0][2*kbi+1][0], pf[0][2*kbi+1][1] };
            uint32_t a1[4] = { pf[1][2*kbi][0], pf[1][2*kbi][1],
                               pf[1][2*kbi+1][0], pf[1][2*kbi+1][1] };
#pragma unroll
            for (int ntp = 0; ntp < 4; ntp++) {
                uint32_t bf[4];
                ldsm_x4(bf, vlast + nRb + ntp * 2048 + kSw[kbi]);
                mma_f16(o[0][2 * ntp],     a0, bf[0], bf[1]);
                mma_f16(o[1][2 * ntp],     a1, bf[0], bf[1]);
                mma_f16(o[0][2 * ntp + 1], a0, bf[2], bf[3]);
                mma_f16(o[1][2 * ntp + 1], a1, bf[2], bf[3]);
            }
            mma_f16(lacc[0], a0, ONES_H2, ONES_H2);
            mma_f16(lacc[1], a1, ONES_H2, ONES_H2);
        }
    }

    // finalize -> O half [B,N,DMODEL]
    int b = bh >> 4, h = bh & 15;
#pragma unroll
    for (int mt = 0; mt < 2; mt++) {
        float inv0 = 1.f / lacc[mt][0], inv1 = 1.f / lacc[mt][2];
        int n0 = qb * 128 + warp * 32 + mt * 16 + s;
        size_t base0 = ((size_t)(b * SEQ + n0)) * DMODEL + h * HDIM;
        size_t base1 = ((size_t)(b * SEQ + n0 + 8)) * DMODEL + h * HDIM;
#pragma unroll
        for (int nt = 0; nt < 8; nt++) {
            int c0 = nt * 8 + 2 * q;
            *(uint32_t*)&O[base0 + c0] = pack_h2(o[mt][nt][0] * inv0, o[mt][nt][1] * inv0);
            *(uint32_t*)&O[base1 + c0] = pack_h2(o[mt][nt][2] * inv1, o[mt][nt][3] * inv1);
        }
    }
}

// ---------------------------------------------------------------------------
extern "C" void kernel_launch(void* const* d_in, const int* in_sizes, int n_in,
                              void* d_out, int out_size)
{
    const float* x    = (const float*)d_in[0];
    const float* qpos = (const float*)d_in[1];
    const float* kpos = (const float*)d_in[2];
    const float* Wq = (const float*)d_in[3];
    const float* bq = (const float*)d_in[4];
    const float* Wk = (const float*)d_in[5];
    const float* bk = (const float*)d_in[6];
    const float* Wv = (const float*)d_in[7];
    const float* bv = (const float*)d_in[8];
    const float* Wo = (const float*)d_in[9];
    const float* bo = (const float*)d_in[10];
    float* out = (float*)d_out;

    __half *pq, *pk, *pv, *po, *pxh, *pwh;
    cudaGetSymbolAddress((void**)&pq, g_q);
    cudaGetSymbolAddress((void**)&pk, g_k);
    cudaGetSymbolAddress((void**)&pv, g_v);
    cudaGetSymbolAddress((void**)&po, g_o);
    cudaGetSymbolAddress((void**)&pxh, g_xh);
    cudaGetSymbolAddress((void**)&pwh, g_wh);

    cudaFuncSetAttribute(gemm_mma_kernel,
                         cudaFuncAttributeMaxDynamicSharedMemorySize, GEMM_SMEM);
    cudaFuncSetAttribute(attn_f16_kernel,
                         cudaFuncAttributeMaxDynamicSharedMemorySize, ATTN_SMEM);

    // one merged pre-convert launch
    CvtArgs ca;
    ca.src[0] = (const float4*)x;
    ca.src[1] = (const float4*)Wq;
    ca.src[2] = (const float4*)Wk;
    ca.src[3] = (const float4*)Wv;
    ca.src[4] = (const float4*)Wo;
    cvt_all_kernel<<<(NX4 + 4 * NW4) / 256, 256>>>(ca, (uint2*)pxh, (uint2*)pwh);

    // fused QKV projection (+rope; q pre-scaled by 0.125*log2e; V transposed)
    GemmArgs qkv;
    qkv.A = pxh;
    qkv.W[0] = pwh; qkv.W[1] = pwh + DMODEL * DMODEL; qkv.W[2] = pwh + 2 * DMODEL * DMODEL;
    qkv.bias[0] = bq; qkv.bias[1] = bk; qkv.bias[2] = bv;
    qkv.C[0] = pq; qkv.C[1] = pk; qkv.C[2] = pv;
    qkv.pos[0] = qpos; qkv.pos[1] = kpos; qkv.pos[2] = nullptr;
    qkv.layout_bhnd = 1;
    gemm_mma_kernel<<<dim3(24, 32), 128, GEMM_SMEM>>>(qkv);

    // attention (R14 config: 128 q-rows per CTA, 4 warps)
    attn_f16_kernel<<<BATCH * NHEADS * (SEQ / 128), 128, ATTN_SMEM>>>(pq, pk, pv, po);

    // output projection
    GemmArgs op;
    op.A = po;
    op.W[0] = op.W[1] = op.W[2] = pwh + 3 * DMODEL * DMODEL;
    op.bias[0] = op.bias[1] = op.bias[2] = bo;
    op.C[0] = op.C[1] = op.C[2] = out;
    op.pos[0] = op.pos[1] = op.pos[2] = nullptr;
    op.layout_bhnd = 0;
    gemm_mma_kernel<<<dim3(8, 32), 128, GEMM_SMEM>>>(op);
}